// round 14
// baseline (speedup 1.0000x reference)
#include <cuda_runtime.h>
#include <cuda_fp16.h>
#include <cstdint>
#include <math.h>

// ---------------- problem constants ----------------
#define B    8
#define S    512
#define E    768
#define NH   12
#define DH   64
#define FF   3072
#define L    6
#define CC   10
#define M4   (B*S)
#define HSZ  (S*DH)
#define NHEAD (B*NH)
#define EPSL 1e-5f
#define SE   (S*E)
#define C_EXP2 0.18033688011112042f  // 0.125 * log2(e), folded into Q

#define EE   (E*E)
#define EF   (E*FF)
#define LW   (4*EE + 2*EF)
#define OFF_Q 0
#define OFF_K EE
#define OFF_V (2*EE)
#define OFF_O (3*EE)
#define OFF_1 (4*EE)
#define OFF_2 (4*EE + EF)

// ---------------- scratch (device globals) ----------------
__device__ float g_h [M4*E];
__device__ float g_t [M4*E];                    // cls partials
__device__ __half g_th[M4*E];                   // pre-LN buffer (fp16)
__device__ __half g_hh[M4*E];
__device__ __half g_qkv[3*M4*E];
__device__ __half g_ch[M4*E];
__device__ __half g_fh[M4*FF];
__device__ __half g_wh[(size_t)L*LW];
__device__ float g_bqkv[L*3*E];
__device__ float g_wct[(size_t)CC*SE];          // transposed classifier weights

// ---------------- asm helpers ----------------
__device__ __forceinline__ uint32_t smem_u32(const void* p) {
    uint32_t a;
    asm("{ .reg .u64 t; cvta.to.shared.u64 t, %1; cvt.u32.u64 %0, t; }" : "=r"(a) : "l"(p));
    return a;
}
__device__ __forceinline__ void ldsm4(uint32_t* r, uint32_t a) {
    asm volatile("ldmatrix.sync.aligned.m8n8.x4.shared.b16 {%0,%1,%2,%3}, [%4];"
        : "=r"(r[0]), "=r"(r[1]), "=r"(r[2]), "=r"(r[3]) : "r"(a));
}
__device__ __forceinline__ void ldsm4t(uint32_t* r, uint32_t a) {
    asm volatile("ldmatrix.sync.aligned.m8n8.x4.trans.shared.b16 {%0,%1,%2,%3}, [%4];"
        : "=r"(r[0]), "=r"(r[1]), "=r"(r[2]), "=r"(r[3]) : "r"(a));
}
__device__ __forceinline__ void mma_f16(float* c, const uint32_t* a, const uint32_t* b) {
    asm volatile("mma.sync.aligned.m16n8k16.row.col.f32.f16.f16.f32 "
        "{%0,%1,%2,%3}, {%4,%5,%6,%7}, {%8,%9}, {%0,%1,%2,%3};"
        : "+f"(c[0]), "+f"(c[1]), "+f"(c[2]), "+f"(c[3])
        : "r"(a[0]), "r"(a[1]), "r"(a[2]), "r"(a[3]), "r"(b[0]), "r"(b[1]));
}
__device__ __forceinline__ uint32_t ex2_h2(uint32_t x) {
    uint32_t r;
    asm("ex2.approx.f16x2 %0, %1;" : "=r"(r) : "r"(x));
    return r;
}
#define CPA(dst, src) asm volatile("cp.async.cg.shared.global [%0], [%1], 16;" :: "r"(dst), "l"(src))
#define CPC() asm volatile("cp.async.commit_group;" ::: "memory")
#define CPW(n) asm volatile("cp.async.wait_group %0;" :: "n"(n) : "memory")

// ================= HMMA GEMM (fp16 in, fp32 accum) =================
template<int BM, int BN>
__global__ void __launch_bounds__(256, (BM == 128) ? 2 : 3)
k_mma(const __half* __restrict__ Ah, const __half* __restrict__ Bh,
      const float* __restrict__ bias, const float* __restrict__ res,
      float* __restrict__ Cf, __half* __restrict__ Chi,
      int N, int K, size_t sAz, size_t sBz, size_t sCz, size_t bsz,
      float scale0, float scale, int relu) {
    extern __shared__ char sm[];
    constexpr int WM  = BM / 32;
    constexpr int WN  = 8 / WM;
    constexpr int WTN = BN / WN;
    constexpr int MF  = 2;
    constexpr int NF  = WTN / 8;
    constexpr int ATILE  = BM * 80;
    constexpr int BPITCH = (BN + 8) * 2;
    constexpr int BTILE  = 32 * BPITCH;
    constexpr int STAGE  = ATILE + BTILE;

    const uint32_t smb = smem_u32(sm);
    const int tid = threadIdx.x, lane = tid & 31, wid = tid >> 5;
    const int wm = wid / WN, wn = wid % WN;
    const int bm = blockIdx.y * BM, bn = blockIdx.x * BN;
    const size_t zA = (size_t)blockIdx.z * sAz, zB = (size_t)blockIdx.z * sBz;
    const __half* pA = Ah + zA + (size_t)bm * K;
    const __half* pB = Bh + zB;

    float acc[MF][NF][4];
#pragma unroll
    for (int i = 0; i < MF; i++)
#pragma unroll
        for (int j = 0; j < NF; j++)
#pragma unroll
            for (int q = 0; q < 4; q++) acc[i][j][q] = 0.f;

    const uint32_t a_off = (uint32_t)(lane & 15) * 80 + (uint32_t)(lane >> 4) * 16;
    const uint32_t b_off = (uint32_t)(lane & 15) * BPITCH + (uint32_t)(lane >> 4) * 16;

    const int KT = K >> 5;

    auto load_stage = [&](int s, int kt) {
        const int k0 = kt << 5;
        const uint32_t base = smb + s * STAGE;
#pragma unroll 2
        for (int cid = tid; cid < BM * 4; cid += 256) {
            const int row = cid >> 2, p = cid & 3;
            CPA(base + row * 80 + p * 16, pA + (size_t)row * K + k0 + p * 8);
        }
#pragma unroll 2
        for (int cid = tid; cid < 32 * (BN / 8); cid += 256) {
            const int row = cid / (BN / 8), c = cid % (BN / 8);
            CPA(base + ATILE + row * BPITCH + c * 16,
                pB + (size_t)(k0 + row) * N + bn + c * 8);
        }
    };

    load_stage(0, 0); CPC();
    if (KT > 1) { load_stage(1, 1); CPC(); }

    for (int kt = 0; kt < KT; ++kt) {
        const int stg = kt & 3;
        if (kt + 2 < KT) { load_stage((kt + 2) & 3, kt + 2); CPC(); CPW(2); }
        else if (kt + 1 < KT) CPW(1);
        else CPW(0);
        __syncthreads();

        const uint32_t stageB = smb + stg * STAGE;
        const uint32_t aB = stageB + wm * 32 * 80 + a_off;
        const uint32_t bB = stageB + ATILE + wn * WTN * 2 + b_off;
#pragma unroll
        for (int ks = 0; ks < 2; ++ks) {
            uint32_t aR[MF][4], bR[(NF + 1) / 2][4];
#pragma unroll
            for (int n2 = 0; n2 < NF / 2; n2++)
                ldsm4t(bR[n2], bB + ks * 16 * BPITCH + n2 * 32);
#pragma unroll
            for (int mi = 0; mi < MF; mi++)
                ldsm4(aR[mi], aB + mi * 16 * 80 + ks * 32);

#pragma unroll
            for (int mi = 0; mi < MF; mi++)
#pragma unroll
                for (int n2 = 0; n2 < NF / 2; n2++) {
                    mma_f16(acc[mi][n2 * 2],     aR[mi], &bR[n2][0]);
                    mma_f16(acc[mi][n2 * 2 + 1], aR[mi], &bR[n2][2]);
                }
        }
    }

    // ---- epilogue ----
    const float sc = (blockIdx.z == 0) ? scale0 : scale;
    const size_t cz = (size_t)blockIdx.z * sCz;
    const float* bz = bias ? bias + (size_t)blockIdx.z * bsz : nullptr;
    const int r0 = bm + wm * 32 + (lane >> 2);
    const int c0 = bn + wn * WTN + (lane & 3) * 2;

#pragma unroll
    for (int mi = 0; mi < MF; mi++) {
#pragma unroll
        for (int ni = 0; ni < NF; ni++) {
            const int col = c0 + ni * 8;
#pragma unroll
            for (int half = 0; half < 2; half++) {
                const int row = r0 + mi * 16 + half * 8;
                float v0 = acc[mi][ni][half * 2]     * sc;
                float v1 = acc[mi][ni][half * 2 + 1] * sc;
                if (bz) { v0 += bz[col]; v1 += bz[col + 1]; }
                if (relu) { v0 = fmaxf(v0, 0.f); v1 = fmaxf(v1, 0.f); }
                if (res) {
                    const float2 rv = *(const float2*)&res[(size_t)row * N + col];
                    v0 += rv.x; v1 += rv.y;
                }
                const size_t o = cz + (size_t)row * N + col;
                if (Cf) { float2 f = {v0, v1}; *(float2*)&Cf[o] = f; }
                if (Chi) {
                    float2 fv; fv.x = v0; fv.y = v1;
                    *(__half2*)&Chi[o] = __float22half2_rn(fv);
                }
            }
        }
    }
}

// ================= fused attention — 3-stage KV ring, 1 barrier/iter =========
#define APITCH 144
#define QBYTES (128*APITCH)   // 18432
#define KVBYTES (2*64*APITCH) // 18432 per stage (K then V)
#define AT_SMEM (QBYTES + 3*KVBYTES)  // 73728

__global__ void __launch_bounds__(256, 3)
k_attn(const __half* __restrict__ q, const __half* __restrict__ k,
       const __half* __restrict__ v, __half* __restrict__ och) {
    extern __shared__ char sm[];
    const uint32_t smb = smem_u32(sm);
    const int tid = threadIdx.x, lane = tid & 31, w = tid >> 5;
    const int z = blockIdx.y, qb = blockIdx.x;
    const __half* pQ = q + (size_t)z * HSZ + (size_t)qb * 128 * DH;
    const __half* pK = k + (size_t)z * HSZ;
    const __half* pV = v + (size_t)z * HSZ;

    const uint32_t a_off  = (uint32_t)(lane & 15) * APITCH + (uint32_t)(lane >> 4) * 16;
    const uint32_t bs_off = (uint32_t)((lane & 7) + ((lane >> 1) & 8)) * APITCH
                          + (uint32_t)((lane >> 3) & 1) * 16;
    const uint32_t bt_off = a_off;

    auto loadQ = [&]() {
#pragma unroll
        for (int cid = tid; cid < 1024; cid += 256) {
            const int row = cid >> 3, p = cid & 7;
            CPA(smb + row * APITCH + p * 16, pQ + (size_t)row * DH + p * 8);
        }
    };
    auto loadKV = [&](int t) {
        const uint32_t kb = smb + QBYTES + (t % 3) * KVBYTES;
        const uint32_t vb = kb + 64 * APITCH;
        const __half* sk = pK + (size_t)t * 64 * DH;
        const __half* sv = pV + (size_t)t * 64 * DH;
#pragma unroll
        for (int cid = tid; cid < 512; cid += 256) {
            const int row = cid >> 3, p = cid & 7;
            CPA(kb + row * APITCH + p * 16, sk + (size_t)row * DH + p * 8);
            CPA(vb + row * APITCH + p * 16, sv + (size_t)row * DH + p * 8);
        }
    };

    loadQ(); loadKV(0); CPC();
    loadKV(1); CPC();

    float oacc[8][4];
#pragma unroll
    for (int j = 0; j < 8; j++)
#pragma unroll
        for (int qq = 0; qq < 4; qq++) oacc[j][qq] = 0.f;
    float l0 = 0.f, l1 = 0.f;

    const uint32_t qbase = smb + w * 16 * APITCH + a_off;
    const __half2 clampv = __floats2half2_rn(14.f, 14.f);

    for (int t = 0; t < 8; ++t) {
        if (t + 1 < 8) CPW(1);
        else CPW(0);
        __syncthreads();
        // prefetch t+2 AFTER barrier: stage (t+2)%3 == (t-1)%3 was read at t-1,
        // and all warps finished t-1 before this barrier.
        if (t + 2 < 8) { loadKV(t + 2); CPC(); }

        // ---- S = Q K^T (logits pre-scaled via Q) ----
        const uint32_t kbase = smb + QBYTES + (t % 3) * KVBYTES;
        float sacc[8][4];
#pragma unroll
        for (int j = 0; j < 8; j++)
#pragma unroll
            for (int qq = 0; qq < 4; qq++) sacc[j][qq] = 0.f;
#pragma unroll
        for (int kc = 0; kc < 4; kc++) {
            uint32_t qf[4];
            ldsm4(qf, qbase + kc * 32);
#pragma unroll
            for (int n2 = 0; n2 < 4; n2++) {
                uint32_t kb[4];
                ldsm4(kb, kbase + n2 * 16 * APITCH + kc * 32 + bs_off);
                mma_f16(sacc[n2 * 2],     qf, &kb[0]);
                mma_f16(sacc[n2 * 2 + 1], qf, &kb[2]);
            }
        }

        // ---- P = exp2(clamp(S)) fp16x2 ----
        uint32_t pp0[8], pp1[8];
#pragma unroll
        for (int j = 0; j < 8; j++) {
            __half2 a = __floats2half2_rn(sacc[j][0], sacc[j][1]);
            __half2 b = __floats2half2_rn(sacc[j][2], sacc[j][3]);
            a = __hmin2(a, clampv);
            b = __hmin2(b, clampv);
            pp0[j] = ex2_h2(*(const uint32_t*)&a);
            pp1[j] = ex2_h2(*(const uint32_t*)&b);
        }

        // ---- O += P V ----
        const uint32_t vbase = kbase + 64 * APITCH;
#pragma unroll
        for (int kc = 0; kc < 4; kc++) {
            uint32_t pa[4];
            pa[0] = pp0[2 * kc];     pa[1] = pp1[2 * kc];
            pa[2] = pp0[2 * kc + 1]; pa[3] = pp1[2 * kc + 1];
#pragma unroll
            for (int n2 = 0; n2 < 4; n2++) {
                uint32_t vb[4];
                ldsm4t(vb, vbase + kc * 16 * APITCH + n2 * 32 + bt_off);
                mma_f16(oacc[n2 * 2],     pa, &vb[0]);
                mma_f16(oacc[n2 * 2 + 1], pa, &vb[2]);
            }
        }

        // ---- l accumulation in the MMA shadow ----
#pragma unroll
        for (int j = 0; j < 8; j++) {
            const float2 fa = __half22float2(*(const __half2*)&pp0[j]);
            const float2 fb = __half22float2(*(const __half2*)&pp1[j]);
            l0 += fa.x + fa.y;
            l1 += fb.x + fb.y;
        }
        __syncthreads();
    }

#pragma unroll
    for (int off = 1; off <= 2; off <<= 1) {
        l0 += __shfl_xor_sync(~0u, l0, off);
        l1 += __shfl_xor_sync(~0u, l1, off);
    }
    const float inv0 = 1.f / l0, inv1 = 1.f / l1;
    const int r0 = qb * 128 + w * 16 + (lane >> 2);
    __half* po = och + (size_t)z * HSZ;
#pragma unroll
    for (int j = 0; j < 8; j++) {
        const int col = j * 8 + (lane & 3) * 2;
        *(__half2*)(po + (size_t)r0 * DH + col) =
            __floats2half2_rn(oacc[j][0] * inv0, oacc[j][1] * inv0);
        *(__half2*)(po + (size_t)(r0 + 8) * DH + col) =
            __floats2half2_rn(oacc[j][2] * inv1, oacc[j][3] * inv1);
    }
}

// ---------------- fused weight fp16 convert + qkv bias pack ----------------
__global__ void k_prep(const float* __restrict__ Wq, const float* __restrict__ Wk,
                       const float* __restrict__ Wv, const float* __restrict__ Wo,
                       const float* __restrict__ W1, const float* __restrict__ W2,
                       __half* __restrict__ wh,
                       const float* __restrict__ bq, const float* __restrict__ bk,
                       const float* __restrict__ bv, float* __restrict__ bqkv) {
    const int l = blockIdx.y;
    if (blockIdx.x < 9) {
        const int j = blockIdx.x * 256 + threadIdx.x;
        if (j < 3 * E) {
            float val;
            if (j < E)            val = bq[(size_t)l * E + j] * C_EXP2;
            else if (j < 2 * E)   val = bk[(size_t)l * E + j - E];
            else                  val = bv[(size_t)l * E + j - 2 * E];
            bqkv[(size_t)l * 3 * E + j] = val;
        }
    }
    const size_t i = ((size_t)blockIdx.x * 256 + threadIdx.x) * 16;
    if (i >= LW) return;
    const float* src;
    if (i < 4 * (size_t)EE) {
        const int ty = (int)(i / EE);
        const float* base = (ty == 0) ? Wq : (ty == 1) ? Wk : (ty == 2) ? Wv : Wo;
        src = base + (size_t)l * EE + (i - (size_t)ty * EE);
    } else if (i < (size_t)OFF_2) {
        src = W1 + (size_t)l * EF + (i - OFF_1);
    } else {
        src = W2 + (size_t)l * EF + (i - OFF_2);
    }
    uint32_t hi[8];
#pragma unroll
    for (int g4 = 0; g4 < 4; g4++) {
        const float4 v = *(const float4*)(src + g4 * 4);
        const __half2 h0 = __floats2half2_rn(v.x, v.y);
        const __half2 h1 = __floats2half2_rn(v.z, v.w);
        hi[g4 * 2]     = *(const uint32_t*)&h0;
        hi[g4 * 2 + 1] = *(const uint32_t*)&h1;
    }
    __half* dst = wh + (size_t)l * LW + i;
    *(uint4*)dst       = *(uint4*)hi;
    *(uint4*)(dst + 8) = *(uint4*)(hi + 4);
}

// ---------------- classifier weight transpose: Wc[SE,CC] -> WcT[CC,SE] --------
__global__ void k_wct(const float* __restrict__ Wc, float* __restrict__ wct) {
    __shared__ float t[2560];             // 256 rows x 10 cols
    const int i0 = blockIdx.x * 256;      // row block
    const int tid = threadIdx.x;
    for (int j = tid; j < 2560; j += 256)
        t[j] = Wc[(size_t)i0 * CC + j];
    __syncthreads();
    for (int c = 0; c < CC; c++)
        wct[(size_t)c * SE + i0 + tid] = t[tid * CC + c];
}

// ---------------- embedding gather ----------------
__global__ void k_embed(const int* __restrict__ x, const float* __restrict__ emb,
                        float* __restrict__ h, __half* __restrict__ hh) {
    const int row = blockIdx.x;
    const int tok = x[row];
    for (int i = threadIdx.x; i < E; i += 256) {
        const float v = emb[(size_t)tok * E + i];
        const size_t o = (size_t)row * E + i;
        h[o] = v;
        hh[o] = __float2half(v);
    }
}

// ---------------- layernorm: fp16 in, fp32+fp16 out, warp per row ----------
__global__ void k_ln(const __half* __restrict__ in, float* __restrict__ out,
                     __half* __restrict__ oh,
                     const float* __restrict__ g, const float* __restrict__ b) {
    const int w = threadIdx.x >> 5, lane = threadIdx.x & 31;
    const int row = blockIdx.x * 8 + w;
    const __half* p = in + (size_t)row * E;

    float x[24];
    float s = 0.f, q = 0.f;
#pragma unroll
    for (int i = 0; i < 3; i++) {
        const uint4 u = *(const uint4*)(p + 8 * (lane + 32 * i));
        const uint32_t* uw = (const uint32_t*)&u;
#pragma unroll
        for (int j = 0; j < 4; j++) {
            const float2 f = __half22float2(*(const __half2*)&uw[j]);
            x[i * 8 + j * 2]     = f.x;
            x[i * 8 + j * 2 + 1] = f.y;
        }
    }
#pragma unroll
    for (int e = 0; e < 24; e++) { s += x[e]; q += x[e] * x[e]; }
#pragma unroll
    for (int off = 16; off; off >>= 1) {
        s += __shfl_xor_sync(~0u, s, off);
        q += __shfl_xor_sync(~0u, q, off);
    }
    const float mean = s * (1.0f / E);
    const float var  = q * (1.0f / E) - mean * mean;
    const float inv  = rsqrtf(var + EPSL);

    float* po = out + (size_t)row * E;
    __half* ph = oh + (size_t)row * E;
#pragma unroll
    for (int i = 0; i < 3; i++) {
        const int c8 = 8 * (lane + 32 * i);
        float v[8];
#pragma unroll
        for (int j = 0; j < 8; j++)
            v[j] = (x[i * 8 + j] - mean) * inv * g[c8 + j] + b[c8 + j];
        *(float4*)(po + c8)     = *(float4*)&v[0];
        *(float4*)(po + c8 + 4) = *(float4*)&v[4];
        uint32_t hp[4];
#pragma unroll
        for (int j = 0; j < 4; j++) {
            const __half2 h2 = __floats2half2_rn(v[j * 2], v[j * 2 + 1]);
            hp[j] = *(const uint32_t*)&h2;
        }
        *(uint4*)(ph + c8) = *(uint4*)hp;
    }
}

// ---------------- classifier: coalesced via WcT ----------------
#define CLS_P 37
#define CLS_CHUNK 10752     // 37*10752 >= SE; last block partial
__global__ void k_cls1(const float* __restrict__ h, const float* __restrict__ wct,
                       float* __restrict__ part) {
    __shared__ float red[256];
    const int bb = blockIdx.x, p = blockIdx.y, t = threadIdx.x;
    const float* hr = h + (size_t)bb * SE;
    const int i0 = p * CLS_CHUNK;
    const int iend = (i0 + CLS_CHUNK < SE) ? i0 + CLS_CHUNK : SE;
    float a[CC];
#pragma unroll
    for (int c = 0; c < CC; c++) a[c] = 0.f;
    for (int i = i0 + t * 4; i < iend; i += 1024) {
        const float4 hv = *(const float4*)&hr[i];
#pragma unroll
        for (int c = 0; c < CC; c++) {
            const float4 wv = *(const float4*)&wct[(size_t)c * SE + i];
            a[c] = fmaf(hv.x, wv.x, fmaf(hv.y, wv.y, fmaf(hv.z, wv.z, fmaf(hv.w, wv.w, a[c]))));
        }
    }
#pragma unroll
    for (int c = 0; c < CC; c++) {
        red[t] = a[c]; __syncthreads();
        for (int k = 128; k > 0; k >>= 1) {
            if (t < k) red[t] += red[t + k];
            __syncthreads();
        }
        if (t == 0) part[((size_t)bb * CLS_P + p) * CC + c] = red[0];
        __syncthreads();
    }
}
__global__ void k_cls2(const float* __restrict__ part, const float* __restrict__ bc,
                       float* __restrict__ out) {
    const int t = threadIdx.x;
    if (t < B * CC) {
        const int bb = t / CC, c = t % CC;
        float s = bc[c];
        for (int p = 0; p < CLS_P; p++) s += part[((size_t)bb * CLS_P + p) * CC + c];
        out[t] = s;
    }
}

// ---------------- host ----------------
extern "C" void kernel_launch(void* const* d_in, const int* in_sizes, int n_in,
                              void* d_out, int out_size) {
    const int*   x    = (const int*)  d_in[0];
    const float* emb  = (const float*)d_in[1];
    const float* Wq   = (const float*)d_in[2];
    const float* bq   = (const float*)d_in[3];
    const float* Wk   = (const float*)d_in[4];
    const float* bk   = (const float*)d_in[5];
    const float* Wv   = (const float*)d_in[6];
    const float* bv   = (const float*)d_in[7];
    const float* Wo   = (const float*)d_in[8];
    const float* bo   = (const float*)d_in[9];
    const float* ln1g = (const float*)d_in[10];
    const float* ln1b = (const float*)d_in[11];
    const float* W1   = (const float*)d_in[12];
    const float* b1   = (const float*)d_in[13];
    const float* W2   = (const float*)d_in[14];
    const float* b2   = (const float*)d_in[15];
    const float* ln2g = (const float*)d_in[16];
    const float* ln2b = (const float*)d_in[17];
    const float* Wc   = (const float*)d_in[18];
    const float* bc   = (const float*)d_in[19];
    float* out = (float*)d_out;

    float *h, *t, *bqkv, *wct;
    __half *hh, *th, *qkv, *ch, *fh, *wh;
    cudaGetSymbolAddress((void**)&h,   g_h);
    cudaGetSymbolAddress((void**)&t,   g_t);
    cudaGetSymbolAddress((void**)&th,  g_th);
    cudaGetSymbolAddress((void**)&hh,  g_hh);
    cudaGetSymbolAddress((void**)&qkv, g_qkv);
    cudaGetSymbolAddress((void**)&ch,  g_ch);
    cudaGetSymbolAddress((void**)&fh,  g_fh);
    cudaGetSymbolAddress((void**)&wh,  g_wh);
    cudaGetSymbolAddress((void**)&bqkv, g_bqkv);
    cudaGetSymbolAddress((void**)&wct, g_wct);

    constexpr int SMEM_QKV = 4 * (128 * 80 + 32 * (128 + 8) * 2);
    constexpr int SMEM_W   = 4 * (64 * 80 + 32 * (128 + 8) * 2);
    cudaFuncSetAttribute(k_mma<128, 128>, cudaFuncAttributeMaxDynamicSharedMemorySize, SMEM_QKV);
    cudaFuncSetAttribute(k_mma<64, 128>,  cudaFuncAttributeMaxDynamicSharedMemorySize, SMEM_W);
    cudaFuncSetAttribute(k_attn,          cudaFuncAttributeMaxDynamicSharedMemorySize, AT_SMEM);

    __half *qh = qkv, *kh = qkv + (size_t)M4 * E, *vh = qkv + (size_t)2 * M4 * E;

    k_prep<<<dim3(LW / 4096, L), 256>>>(Wq, Wk, Wv, Wo, W1, W2, wh, bq, bk, bv, bqkv);
    k_wct<<<SE / 256, 256>>>(Wc, wct);
    k_embed<<<M4, 256>>>(x, emb, h, hh);

    const dim3 gQKV(6, 32, 3);
    const dim3 gEE64(6, 64);
    const dim3 gF164(24, 64);
    const dim3 gAt(4, NHEAD);

    for (int l = 0; l < L; l++) {
        const size_t wb = (size_t)l * LW;

        // fused QKV (q pre-scaled by 0.125*log2e)
        k_mma<128, 128><<<gQKV, 256, SMEM_QKV>>>(hh, wh + wb + OFF_Q,
            bqkv + (size_t)l * 3 * E, nullptr, nullptr, qkv,
            E, E, 0, (size_t)EE, (size_t)M4 * E, E, C_EXP2, 1.f, 0);

        // fused attention
        k_attn<<<gAt, 256, AT_SMEM>>>(qh, kh, vh, ch);

        // Wo + residual -> th (fp16) -> LN1
        k_mma<64, 128><<<gEE64, 256, SMEM_W>>>(ch, wh + wb + OFF_O,
            bo + (size_t)l * E, h, nullptr, th,
            E, E, 0, 0, 0, 0, 1.f, 1.f, 0);
        k_ln<<<M4 / 8, 256>>>(th, h, hh, ln1g + (size_t)l * E, ln1b + (size_t)l * E);

        // FFN
        k_mma<64, 128><<<gF164, 256, SMEM_W>>>(hh, wh + wb + OFF_1,
            b1 + (size_t)l * FF, nullptr, nullptr, fh,
            FF, E, 0, 0, 0, 0, 1.f, 1.f, 1);
        k_mma<64, 128><<<gEE64, 256, SMEM_W>>>(fh, wh + wb + OFF_2,
            b2 + (size_t)l * E, h, nullptr, th,
            E, FF, 0, 0, 0, 0, 1.f, 1.f, 0);
        k_ln<<<M4 / 8, 256>>>(th, h, hh, ln2g + (size_t)l * E, ln2b + (size_t)l * E);
    }

    // classifier
    k_cls1<<<dim3(B, CLS_P), 256>>>(h, wct, t);
    k_cls2<<<1, 128>>>(t, bc, out);
}

// round 15
// speedup vs baseline: 1.0432x; 1.0432x over previous
#include <cuda_runtime.h>
#include <cuda_fp16.h>
#include <cstdint>
#include <math.h>

// ---------------- problem constants ----------------
#define B    8
#define S    512
#define E    768
#define NH   12
#define DH   64
#define FF   3072
#define L    6
#define CC   10
#define M4   (B*S)
#define HSZ  (S*DH)
#define NHEAD (B*NH)
#define EPSL 1e-5f
#define SE   (S*E)
#define C_EXP2 0.18033688011112042f  // 0.125 * log2(e), folded into Q

#define EE   (E*E)
#define EF   (E*FF)
#define LW   (4*EE + 2*EF)
#define OFF_Q 0
#define OFF_K EE
#define OFF_V (2*EE)
#define OFF_O (3*EE)
#define OFF_1 (4*EE)
#define OFF_2 (4*EE + EF)

// ---------------- scratch (device globals) ----------------
__device__ float g_h [M4*E];
__device__ float g_t [M4*E];                    // pre-LN buffer (fp32); cls partials
__device__ __half g_hh[M4*E];
__device__ __half g_qkv[3*M4*E];
__device__ __half g_ch[M4*E];
__device__ __half g_fh[M4*FF];
__device__ __half g_wh[(size_t)L*LW];
__device__ float g_bqkv[L*3*E];
__device__ float g_wct[(size_t)CC*SE];          // transposed classifier weights
__device__ float g_part[B*37*CC];               // cls partials

// ---------------- asm helpers ----------------
__device__ __forceinline__ uint32_t smem_u32(const void* p) {
    uint32_t a;
    asm("{ .reg .u64 t; cvta.to.shared.u64 t, %1; cvt.u32.u64 %0, t; }" : "=r"(a) : "l"(p));
    return a;
}
__device__ __forceinline__ void ldsm4(uint32_t* r, uint32_t a) {
    asm volatile("ldmatrix.sync.aligned.m8n8.x4.shared.b16 {%0,%1,%2,%3}, [%4];"
        : "=r"(r[0]), "=r"(r[1]), "=r"(r[2]), "=r"(r[3]) : "r"(a));
}
__device__ __forceinline__ void ldsm4t(uint32_t* r, uint32_t a) {
    asm volatile("ldmatrix.sync.aligned.m8n8.x4.trans.shared.b16 {%0,%1,%2,%3}, [%4];"
        : "=r"(r[0]), "=r"(r[1]), "=r"(r[2]), "=r"(r[3]) : "r"(a));
}
__device__ __forceinline__ void mma_f16(float* c, const uint32_t* a, const uint32_t* b) {
    asm volatile("mma.sync.aligned.m16n8k16.row.col.f32.f16.f16.f32 "
        "{%0,%1,%2,%3}, {%4,%5,%6,%7}, {%8,%9}, {%0,%1,%2,%3};"
        : "+f"(c[0]), "+f"(c[1]), "+f"(c[2]), "+f"(c[3])
        : "r"(a[0]), "r"(a[1]), "r"(a[2]), "r"(a[3]), "r"(b[0]), "r"(b[1]));
}
__device__ __forceinline__ uint32_t ex2_h2(uint32_t x) {
    uint32_t r;
    asm("ex2.approx.f16x2 %0, %1;" : "=r"(r) : "r"(x));
    return r;
}
#define CPA(dst, src) asm volatile("cp.async.cg.shared.global [%0], [%1], 16;" :: "r"(dst), "l"(src))
#define CPC() asm volatile("cp.async.commit_group;" ::: "memory")
#define CPW(n) asm volatile("cp.async.wait_group %0;" :: "n"(n) : "memory")

// ================= HMMA GEMM (fp16 in, fp32 accum) =================
// D = sc*sum_k A*B (+bias)(relu)(+res); B stored [K,N] (trans). sc=(z==0)?scale0:scale.
template<int BM, int BN>
__global__ void __launch_bounds__(256, (BM == 128) ? 2 : 3)
k_mma(const __half* __restrict__ Ah, const __half* __restrict__ Bh,
      const float* __restrict__ bias, const float* __restrict__ res,
      float* __restrict__ Cf, __half* __restrict__ Chi,
      int N, int K, size_t sAz, size_t sBz, size_t sCz, size_t bsz,
      float scale0, float scale, int relu) {
    extern __shared__ char sm[];
    constexpr int WM  = BM / 32;
    constexpr int WN  = 8 / WM;
    constexpr int WTN = BN / WN;
    constexpr int MF  = 2;
    constexpr int NF  = WTN / 8;
    constexpr int ATILE  = BM * 80;
    constexpr int BPITCH = (BN + 8) * 2;
    constexpr int BTILE  = 32 * BPITCH;
    constexpr int STAGE  = ATILE + BTILE;

    const uint32_t smb = smem_u32(sm);
    const int tid = threadIdx.x, lane = tid & 31, wid = tid >> 5;
    const int wm = wid / WN, wn = wid % WN;
    const int bm = blockIdx.y * BM, bn = blockIdx.x * BN;
    const size_t zA = (size_t)blockIdx.z * sAz, zB = (size_t)blockIdx.z * sBz;
    const __half* pA = Ah + zA + (size_t)bm * K;
    const __half* pB = Bh + zB;

    float acc[MF][NF][4];
#pragma unroll
    for (int i = 0; i < MF; i++)
#pragma unroll
        for (int j = 0; j < NF; j++)
#pragma unroll
            for (int q = 0; q < 4; q++) acc[i][j][q] = 0.f;

    const uint32_t a_off = (uint32_t)(lane & 15) * 80 + (uint32_t)(lane >> 4) * 16;
    const uint32_t b_off = (uint32_t)(lane & 15) * BPITCH + (uint32_t)(lane >> 4) * 16;

    const int KT = K >> 5;

    auto load_stage = [&](int s, int kt) {
        const int k0 = kt << 5;
        const uint32_t base = smb + s * STAGE;
#pragma unroll 2
        for (int cid = tid; cid < BM * 4; cid += 256) {
            const int row = cid >> 2, p = cid & 3;
            CPA(base + row * 80 + p * 16, pA + (size_t)row * K + k0 + p * 8);
        }
#pragma unroll 2
        for (int cid = tid; cid < 32 * (BN / 8); cid += 256) {
            const int row = cid / (BN / 8), c = cid % (BN / 8);
            CPA(base + ATILE + row * BPITCH + c * 16,
                pB + (size_t)(k0 + row) * N + bn + c * 8);
        }
    };

    load_stage(0, 0); CPC();
    if (KT > 1) { load_stage(1, 1); CPC(); }

    for (int kt = 0; kt < KT; ++kt) {
        const int stg = kt & 3;
        if (kt + 2 < KT) { load_stage((kt + 2) & 3, kt + 2); CPC(); CPW(2); }
        else if (kt + 1 < KT) CPW(1);
        else CPW(0);
        __syncthreads();

        const uint32_t stageB = smb + stg * STAGE;
        const uint32_t aB = stageB + wm * 32 * 80 + a_off;
        const uint32_t bB = stageB + ATILE + wn * WTN * 2 + b_off;
#pragma unroll
        for (int ks = 0; ks < 2; ++ks) {
            uint32_t aR[MF][4], bR[(NF + 1) / 2][4];
#pragma unroll
            for (int n2 = 0; n2 < NF / 2; n2++)
                ldsm4t(bR[n2], bB + ks * 16 * BPITCH + n2 * 32);
#pragma unroll
            for (int mi = 0; mi < MF; mi++)
                ldsm4(aR[mi], aB + mi * 16 * 80 + ks * 32);

#pragma unroll
            for (int mi = 0; mi < MF; mi++)
#pragma unroll
                for (int n2 = 0; n2 < NF / 2; n2++) {
                    mma_f16(acc[mi][n2 * 2],     aR[mi], &bR[n2][0]);
                    mma_f16(acc[mi][n2 * 2 + 1], aR[mi], &bR[n2][2]);
                }
        }
    }

    // ---- epilogue ----
    const float sc = (blockIdx.z == 0) ? scale0 : scale;
    const size_t cz = (size_t)blockIdx.z * sCz;
    const float* bz = bias ? bias + (size_t)blockIdx.z * bsz : nullptr;
    const int r0 = bm + wm * 32 + (lane >> 2);
    const int c0 = bn + wn * WTN + (lane & 3) * 2;

#pragma unroll
    for (int mi = 0; mi < MF; mi++) {
#pragma unroll
        for (int ni = 0; ni < NF; ni++) {
            const int col = c0 + ni * 8;
#pragma unroll
            for (int half = 0; half < 2; half++) {
                const int row = r0 + mi * 16 + half * 8;
                float v0 = acc[mi][ni][half * 2]     * sc;
                float v1 = acc[mi][ni][half * 2 + 1] * sc;
                if (bz) { v0 += bz[col]; v1 += bz[col + 1]; }
                if (relu) { v0 = fmaxf(v0, 0.f); v1 = fmaxf(v1, 0.f); }
                if (res) {
                    const float2 rv = *(const float2*)&res[(size_t)row * N + col];
                    v0 += rv.x; v1 += rv.y;
                }
                const size_t o = cz + (size_t)row * N + col;
                if (Cf) { float2 f = {v0, v1}; *(float2*)&Cf[o] = f; }
                if (Chi) {
                    float2 fv; fv.x = v0; fv.y = v1;
                    *(__half2*)&Chi[o] = __float22half2_rn(fv);
                }
            }
        }
    }
}

// ================= fused attention — no-max fp16-exp softmax (round-13) ======
#define APITCH 144
#define QBYTES (128*APITCH)
#define TBYTES (64*APITCH)
#define AT_SMEM (QBYTES + 4*TBYTES)  // 55296

__global__ void __launch_bounds__(256, 3)
k_attn(const __half* __restrict__ q, const __half* __restrict__ k,
       const __half* __restrict__ v, __half* __restrict__ och) {
    extern __shared__ char sm[];
    const uint32_t smb = smem_u32(sm);
    const uint32_t KOFF = QBYTES, VOFF = QBYTES + 2 * TBYTES;
    const int tid = threadIdx.x, lane = tid & 31, w = tid >> 5;
    const int z = blockIdx.y, qb = blockIdx.x;
    const __half* pQ = q + (size_t)z * HSZ + (size_t)qb * 128 * DH;
    const __half* pK = k + (size_t)z * HSZ;
    const __half* pV = v + (size_t)z * HSZ;

    const uint32_t a_off  = (uint32_t)(lane & 15) * APITCH + (uint32_t)(lane >> 4) * 16;
    const uint32_t bs_off = (uint32_t)((lane & 7) + ((lane >> 1) & 8)) * APITCH
                          + (uint32_t)((lane >> 3) & 1) * 16;
    const uint32_t bt_off = a_off;

    auto loadQ = [&]() {
#pragma unroll
        for (int cid = tid; cid < 1024; cid += 256) {
            const int row = cid >> 3, p = cid & 7;
            CPA(smb + row * APITCH + p * 16, pQ + (size_t)row * DH + p * 8);
        }
    };
    auto loadKV = [&](int t) {
        const uint32_t kb = smb + KOFF + (t & 1) * TBYTES;
        const uint32_t vb = smb + VOFF + (t & 1) * TBYTES;
        const __half* sk = pK + (size_t)t * 64 * DH;
        const __half* sv = pV + (size_t)t * 64 * DH;
#pragma unroll
        for (int cid = tid; cid < 512; cid += 256) {
            const int row = cid >> 3, p = cid & 7;
            CPA(kb + row * APITCH + p * 16, sk + (size_t)row * DH + p * 8);
            CPA(vb + row * APITCH + p * 16, sv + (size_t)row * DH + p * 8);
        }
    };

    loadQ(); loadKV(0); CPC();

    float oacc[8][4];
#pragma unroll
    for (int j = 0; j < 8; j++)
#pragma unroll
        for (int qq = 0; qq < 4; qq++) oacc[j][qq] = 0.f;
    float l0 = 0.f, l1 = 0.f;

    const uint32_t qbase = smb + w * 16 * APITCH + a_off;
    const __half2 clampv = __floats2half2_rn(14.f, 14.f);

    for (int t = 0; t < 8; ++t) {
        if (t + 1 < 8) { loadKV(t + 1); CPC(); CPW(1); }
        else CPW(0);
        __syncthreads();

        // ---- S = Q K^T (logits pre-scaled via Q) ----
        const uint32_t kbase = smb + KOFF + (t & 1) * TBYTES;
        float sacc[8][4];
#pragma unroll
        for (int j = 0; j < 8; j++)
#pragma unroll
            for (int qq = 0; qq < 4; qq++) sacc[j][qq] = 0.f;
#pragma unroll
        for (int kc = 0; kc < 4; kc++) {
            uint32_t qf[4];
            ldsm4(qf, qbase + kc * 32);
#pragma unroll
            for (int n2 = 0; n2 < 4; n2++) {
                uint32_t kb[4];
                ldsm4(kb, kbase + n2 * 16 * APITCH + kc * 32 + bs_off);
                mma_f16(sacc[n2 * 2],     qf, &kb[0]);
                mma_f16(sacc[n2 * 2 + 1], qf, &kb[2]);
            }
        }

        // ---- P = exp2(clamp(S)) fp16x2; l += sums ----
        uint32_t pp0[8], pp1[8];
#pragma unroll
        for (int j = 0; j < 8; j++) {
            __half2 a = __floats2half2_rn(sacc[j][0], sacc[j][1]);
            __half2 b = __floats2half2_rn(sacc[j][2], sacc[j][3]);
            a = __hmin2(a, clampv);
            b = __hmin2(b, clampv);
            pp0[j] = ex2_h2(*(const uint32_t*)&a);
            pp1[j] = ex2_h2(*(const uint32_t*)&b);
            const float2 fa = __half22float2(*(const __half2*)&pp0[j]);
            const float2 fb = __half22float2(*(const __half2*)&pp1[j]);
            l0 += fa.x + fa.y;
            l1 += fb.x + fb.y;
        }

        // ---- O += P V ----
        const uint32_t vbase = smb + VOFF + (t & 1) * TBYTES;
#pragma unroll
        for (int kc = 0; kc < 4; kc++) {
            uint32_t pa[4];
            pa[0] = pp0[2 * kc];     pa[1] = pp1[2 * kc];
            pa[2] = pp0[2 * kc + 1]; pa[3] = pp1[2 * kc + 1];
#pragma unroll
            for (int n2 = 0; n2 < 4; n2++) {
                uint32_t vb[4];
                ldsm4t(vb, vbase + kc * 16 * APITCH + n2 * 32 + bt_off);
                mma_f16(oacc[n2 * 2],     pa, &vb[0]);
                mma_f16(oacc[n2 * 2 + 1], pa, &vb[2]);
            }
        }
        __syncthreads();
    }

#pragma unroll
    for (int off = 1; off <= 2; off <<= 1) {
        l0 += __shfl_xor_sync(~0u, l0, off);
        l1 += __shfl_xor_sync(~0u, l1, off);
    }
    const float inv0 = 1.f / l0, inv1 = 1.f / l1;
    const int r0 = qb * 128 + w * 16 + (lane >> 2);
    __half* po = och + (size_t)z * HSZ;
#pragma unroll
    for (int j = 0; j < 8; j++) {
        const int col = j * 8 + (lane & 3) * 2;
        *(__half2*)(po + (size_t)r0 * DH + col) =
            __floats2half2_rn(oacc[j][0] * inv0, oacc[j][1] * inv0);
        *(__half2*)(po + (size_t)(r0 + 8) * DH + col) =
            __floats2half2_rn(oacc[j][2] * inv1, oacc[j][3] * inv1);
    }
}

// ---------------- fused weight fp16 convert + qkv bias pack ----------------
__global__ void k_prep(const float* __restrict__ Wq, const float* __restrict__ Wk,
                       const float* __restrict__ Wv, const float* __restrict__ Wo,
                       const float* __restrict__ W1, const float* __restrict__ W2,
                       __half* __restrict__ wh,
                       const float* __restrict__ bq, const float* __restrict__ bk,
                       const float* __restrict__ bv, float* __restrict__ bqkv) {
    const int l = blockIdx.y;
    if (blockIdx.x < 9) {
        const int j = blockIdx.x * 256 + threadIdx.x;
        if (j < 3 * E) {
            float val;
            if (j < E)            val = bq[(size_t)l * E + j] * C_EXP2;
            else if (j < 2 * E)   val = bk[(size_t)l * E + j - E];
            else                  val = bv[(size_t)l * E + j - 2 * E];
            bqkv[(size_t)l * 3 * E + j] = val;
        }
    }
    const size_t i = ((size_t)blockIdx.x * 256 + threadIdx.x) * 16;
    if (i >= LW) return;
    const float* src;
    if (i < 4 * (size_t)EE) {
        const int ty = (int)(i / EE);
        const float* base = (ty == 0) ? Wq : (ty == 1) ? Wk : (ty == 2) ? Wv : Wo;
        src = base + (size_t)l * EE + (i - (size_t)ty * EE);
    } else if (i < (size_t)OFF_2) {
        src = W1 + (size_t)l * EF + (i - OFF_1);
    } else {
        src = W2 + (size_t)l * EF + (i - OFF_2);
    }
    uint32_t hi[8];
#pragma unroll
    for (int g4 = 0; g4 < 4; g4++) {
        const float4 v = *(const float4*)(src + g4 * 4);
        const __half2 h0 = __floats2half2_rn(v.x, v.y);
        const __half2 h1 = __floats2half2_rn(v.z, v.w);
        hi[g4 * 2]     = *(const uint32_t*)&h0;
        hi[g4 * 2 + 1] = *(const uint32_t*)&h1;
    }
    __half* dst = wh + (size_t)l * LW + i;
    *(uint4*)dst       = *(uint4*)hi;
    *(uint4*)(dst + 8) = *(uint4*)(hi + 4);
}

// ---------------- classifier weight transpose: Wc[SE,CC] -> WcT[CC,SE] --------
__global__ void k_wct(const float* __restrict__ Wc, float* __restrict__ wct) {
    __shared__ float t[2560];             // 256 rows x 10 cols
    const int i0 = blockIdx.x * 256;
    const int tid = threadIdx.x;
    for (int j = tid; j < 2560; j += 256)
        t[j] = Wc[(size_t)i0 * CC + j];
    __syncthreads();
    for (int c = 0; c < CC; c++)
        wct[(size_t)c * SE + i0 + tid] = t[tid * CC + c];
}

// ---------------- embedding gather ----------------
__global__ void k_embed(const int* __restrict__ x, const float* __restrict__ emb,
                        float* __restrict__ h, __half* __restrict__ hh) {
    const int row = blockIdx.x;
    const int tok = x[row];
    for (int i = threadIdx.x; i < E; i += 256) {
        const float v = emb[(size_t)tok * E + i];
        const size_t o = (size_t)row * E + i;
        h[o] = v;
        hh[o] = __float2half(v);
    }
}

// ---------------- layernorm: fp32 in, fp32 + fp16 out, warp per row ----------
__global__ void k_ln(const float* __restrict__ in, float* __restrict__ out,
                     __half* __restrict__ oh,
                     const float* __restrict__ g, const float* __restrict__ b) {
    const int w = threadIdx.x >> 5, lane = threadIdx.x & 31;
    const int row = blockIdx.x * 8 + w;
    const float* p = in + (size_t)row * E;

    float4 x[6];
    float s = 0.f, q = 0.f;
#pragma unroll
    for (int i = 0; i < 6; i++) {
        x[i] = *(const float4*)(p + 4 * (lane + 32 * i));
        s += x[i].x + x[i].y + x[i].z + x[i].w;
        q += x[i].x * x[i].x + x[i].y * x[i].y + x[i].z * x[i].z + x[i].w * x[i].w;
    }
#pragma unroll
    for (int off = 16; off; off >>= 1) {
        s += __shfl_xor_sync(~0u, s, off);
        q += __shfl_xor_sync(~0u, q, off);
    }
    const float mean = s * (1.0f / E);
    const float var  = q * (1.0f / E) - mean * mean;
    const float inv  = rsqrtf(var + EPSL);

    float* po = out + (size_t)row * E;
    __half* ph = oh + (size_t)row * E;
#pragma unroll
    for (int i = 0; i < 6; i++) {
        const int c4 = 4 * (lane + 32 * i);
        const float4 gv = *(const float4*)(g + c4);
        const float4 bv = *(const float4*)(b + c4);
        float4 v;
        v.x = (x[i].x - mean) * inv * gv.x + bv.x;
        v.y = (x[i].y - mean) * inv * gv.y + bv.y;
        v.z = (x[i].z - mean) * inv * gv.z + bv.z;
        v.w = (x[i].w - mean) * inv * gv.w + bv.w;
        *(float4*)(po + c4) = v;
        uint32_t hp[2];
        const __half2 h0 = __floats2half2_rn(v.x, v.y);
        const __half2 h1 = __floats2half2_rn(v.z, v.w);
        hp[0] = *(const uint32_t*)&h0;
        hp[1] = *(const uint32_t*)&h1;
        *(uint2*)(ph + c4) = *(uint2*)hp;
    }
}

// ---------------- classifier: coalesced via WcT ----------------
#define CLS_P 37
#define CLS_CHUNK 10752
__global__ void k_cls1(const float* __restrict__ h, const float* __restrict__ wct,
                       float* __restrict__ part) {
    __shared__ float red[256];
    const int bb = blockIdx.x, p = blockIdx.y, t = threadIdx.x;
    const float* hr = h + (size_t)bb * SE;
    const int i0 = p * CLS_CHUNK;
    const int iend = (i0 + CLS_CHUNK < SE) ? i0 + CLS_CHUNK : SE;
    float a[CC];
#pragma unroll
    for (int c = 0; c < CC; c++) a[c] = 0.f;
    for (int i = i0 + t * 4; i < iend; i += 1024) {
        const float4 hv = *(const float4*)&hr[i];
#pragma unroll
        for (int c = 0; c < CC; c++) {
            const float4 wv = *(const float4*)&wct[(size_t)c * SE + i];
            a[c] = fmaf(hv.x, wv.x, fmaf(hv.y, wv.y, fmaf(hv.z, wv.z, fmaf(hv.w, wv.w, a[c]))));
        }
    }
#pragma unroll
    for (int c = 0; c < CC; c++) {
        red[t] = a[c]; __syncthreads();
        for (int k = 128; k > 0; k >>= 1) {
            if (t < k) red[t] += red[t + k];
            __syncthreads();
        }
        if (t == 0) part[((size_t)bb * CLS_P + p) * CC + c] = red[0];
        __syncthreads();
    }
}
__global__ void k_cls2(const float* __restrict__ part, const float* __restrict__ bc,
                       float* __restrict__ out) {
    const int t = threadIdx.x;
    if (t < B * CC) {
        const int bb = t / CC, c = t % CC;
        float s = bc[c];
        for (int p = 0; p < CLS_P; p++) s += part[((size_t)bb * CLS_P + p) * CC + c];
        out[t] = s;
    }
}

// ---------------- host ----------------
extern "C" void kernel_launch(void* const* d_in, const int* in_sizes, int n_in,
                              void* d_out, int out_size) {
    const int*   x    = (const int*)  d_in[0];
    const float* emb  = (const float*)d_in[1];
    const float* Wq   = (const float*)d_in[2];
    const float* bq   = (const float*)d_in[3];
    const float* Wk   = (const float*)d_in[4];
    const float* bk   = (const float*)d_in[5];
    const float* Wv   = (const float*)d_in[6];
    const float* bv   = (const float*)d_in[7];
    const float* Wo   = (const float*)d_in[8];
    const float* bo   = (const float*)d_in[9];
    const float* ln1g = (const float*)d_in[10];
    const float* ln1b = (const float*)d_in[11];
    const float* W1   = (const float*)d_in[12];
    const float* b1   = (const float*)d_in[13];
    const float* W2   = (const float*)d_in[14];
    const float* b2   = (const float*)d_in[15];
    const float* ln2g = (const float*)d_in[16];
    const float* ln2b = (const float*)d_in[17];
    const float* Wc   = (const float*)d_in[18];
    const float* bc   = (const float*)d_in[19];
    float* out = (float*)d_out;

    float *h, *t, *bqkv, *wct, *part;
    __half *hh, *qkv, *ch, *fh, *wh;
    cudaGetSymbolAddress((void**)&h,   g_h);
    cudaGetSymbolAddress((void**)&t,   g_t);
    cudaGetSymbolAddress((void**)&hh,  g_hh);
    cudaGetSymbolAddress((void**)&qkv, g_qkv);
    cudaGetSymbolAddress((void**)&ch,  g_ch);
    cudaGetSymbolAddress((void**)&fh,  g_fh);
    cudaGetSymbolAddress((void**)&wh,  g_wh);
    cudaGetSymbolAddress((void**)&bqkv, g_bqkv);
    cudaGetSymbolAddress((void**)&wct, g_wct);
    cudaGetSymbolAddress((void**)&part, g_part);

    constexpr int SMEM_QKV = 4 * (128 * 80 + 32 * (128 + 8) * 2);
    constexpr int SMEM_W   = 4 * (64 * 80 + 32 * (128 + 8) * 2);
    cudaFuncSetAttribute(k_mma<128, 128>, cudaFuncAttributeMaxDynamicSharedMemorySize, SMEM_QKV);
    cudaFuncSetAttribute(k_mma<64, 128>,  cudaFuncAttributeMaxDynamicSharedMemorySize, SMEM_W);
    cudaFuncSetAttribute(k_attn,          cudaFuncAttributeMaxDynamicSharedMemorySize, AT_SMEM);

    __half *qh = qkv, *kh = qkv + (size_t)M4 * E, *vh = qkv + (size_t)2 * M4 * E;

    k_prep<<<dim3(LW / 4096, L), 256>>>(Wq, Wk, Wv, Wo, W1, W2, wh, bq, bk, bv, bqkv);
    k_wct<<<SE / 256, 256>>>(Wc, wct);
    k_embed<<<M4, 256>>>(x, emb, h, hh);

    const dim3 gQKV(6, 32, 3);
    const dim3 gEE64(6, 64);
    const dim3 gF164(24, 64);
    const dim3 gAt(4, NHEAD);

    for (int l = 0; l < L; l++) {
        const size_t wb = (size_t)l * LW;

        // fused QKV (q pre-scaled by 0.125*log2e)
        k_mma<128, 128><<<gQKV, 256, SMEM_QKV>>>(hh, wh + wb + OFF_Q,
            bqkv + (size_t)l * 3 * E, nullptr, nullptr, qkv,
            E, E, 0, (size_t)EE, (size_t)M4 * E, E, C_EXP2, 1.f, 0);

        // fused attention
        k_attn<<<gAt, 256, AT_SMEM>>>(qh, kh, vh, ch);

        // Wo + residual -> t (fp32) -> LN1
        k_mma<64, 128><<<gEE64, 256, SMEM_W>>>(ch, wh + wb + OFF_O,
            bo + (size_t)l * E, h, t, nullptr,
            E, E, 0, 0, 0, 0, 1.f, 1.f, 0);
        k_ln<<<M4 / 8, 256>>>(t, h, hh, ln1g + (size_t)l * E, ln1b + (size_t)l * E);

        // FFN
        k_mma<64, 128><<<gF164, 256, SMEM_W>>>(hh, wh + wb + OFF_1,
            b1 + (size_t)l * FF, nullptr, nullptr, fh,
            FF, E, 0, 0, 0, 0, 1.f, 1.f, 1);
        k_mma<64, 128><<<gEE64, 256, SMEM_W>>>(fh, wh + wb + OFF_2,
            b2 + (size_t)l * E, h, t, nullptr,
            E, FF, 0, 0, 0, 0, 1.f, 1.f, 0);
        k_ln<<<M4 / 8, 256>>>(t, h, hh, ln2g + (size_t)l * E, ln2b + (size_t)l * E);
    }

    // classifier (fp32 exact, coalesced)
    k_cls1<<<dim3(B, CLS_P), 256>>>(h, wct, part);
    k_cls2<<<1, 128>>>(part, bc, out);
}

// round 16
// speedup vs baseline: 1.0523x; 1.0087x over previous
#include <cuda_runtime.h>
#include <cuda_fp16.h>
#include <cstdint>
#include <math.h>

// ---------------- problem constants ----------------
#define B    8
#define S    512
#define E    768
#define NH   12
#define DH   64
#define FF   3072
#define L    6
#define CC   10
#define M4   (B*S)
#define HSZ  (S*DH)
#define NHEAD (B*NH)
#define EPSL 1e-5f
#define SE   (S*E)
#define C_EXP2 0.18033688011112042f  // 0.125 * log2(e), folded into Q

#define EE   (E*E)
#define EF   (E*FF)
#define LW   (4*EE + 2*EF)
#define OFF_Q 0
#define OFF_K EE
#define OFF_V (2*EE)
#define OFF_O (3*EE)
#define OFF_1 (4*EE)
#define OFF_2 (4*EE + EF)

// ---------------- scratch (device globals) ----------------
__device__ float g_h [M4*E];
__device__ float g_t [M4*E];                    // pre-LN buffer (fp32)
__device__ __half g_hh[M4*E];
__device__ __half g_qkv[3*M4*E];
__device__ __half g_ch[M4*E];
__device__ __half g_fh[M4*FF];
__device__ __half g_wh[(size_t)L*LW];
__device__ float g_bqkv[L*3*E];
__device__ float g_wct[(size_t)CC*SE];          // transposed classifier weights
__device__ float g_part[B*37*CC];               // cls partials

// ---------------- asm helpers ----------------
__device__ __forceinline__ uint32_t smem_u32(const void* p) {
    uint32_t a;
    asm("{ .reg .u64 t; cvta.to.shared.u64 t, %1; cvt.u32.u64 %0, t; }" : "=r"(a) : "l"(p));
    return a;
}
__device__ __forceinline__ void ldsm4(uint32_t* r, uint32_t a) {
    asm volatile("ldmatrix.sync.aligned.m8n8.x4.shared.b16 {%0,%1,%2,%3}, [%4];"
        : "=r"(r[0]), "=r"(r[1]), "=r"(r[2]), "=r"(r[3]) : "r"(a));
}
__device__ __forceinline__ void ldsm4t(uint32_t* r, uint32_t a) {
    asm volatile("ldmatrix.sync.aligned.m8n8.x4.trans.shared.b16 {%0,%1,%2,%3}, [%4];"
        : "=r"(r[0]), "=r"(r[1]), "=r"(r[2]), "=r"(r[3]) : "r"(a));
}
__device__ __forceinline__ void mma_f16(float* c, const uint32_t* a, const uint32_t* b) {
    asm volatile("mma.sync.aligned.m16n8k16.row.col.f32.f16.f16.f32 "
        "{%0,%1,%2,%3}, {%4,%5,%6,%7}, {%8,%9}, {%0,%1,%2,%3};"
        : "+f"(c[0]), "+f"(c[1]), "+f"(c[2]), "+f"(c[3])
        : "r"(a[0]), "r"(a[1]), "r"(a[2]), "r"(a[3]), "r"(b[0]), "r"(b[1]));
}
__device__ __forceinline__ uint32_t ex2_h2(uint32_t x) {
    uint32_t r;
    asm("ex2.approx.f16x2 %0, %1;" : "=r"(r) : "r"(x));
    return r;
}
#define CPA(dst, src) asm volatile("cp.async.cg.shared.global [%0], [%1], 16;" :: "r"(dst), "l"(src))
#define CPC() asm volatile("cp.async.commit_group;" ::: "memory")
#define CPW(n) asm volatile("cp.async.wait_group %0;" :: "n"(n) : "memory")

// ================= HMMA GEMM (fp16 in, fp32 accum) =================
template<int BM, int BN>
__global__ void __launch_bounds__(256, (BM == 128) ? 2 : 3)
k_mma(const __half* __restrict__ Ah, const __half* __restrict__ Bh,
      const float* __restrict__ bias, const float* __restrict__ res,
      float* __restrict__ Cf, __half* __restrict__ Chi,
      int N, int K, size_t sAz, size_t sBz, size_t sCz, size_t bsz,
      float scale0, float scale, int relu) {
    extern __shared__ char sm[];
    constexpr int WM  = BM / 32;
    constexpr int WN  = 8 / WM;
    constexpr int WTN = BN / WN;
    constexpr int MF  = 2;
    constexpr int NF  = WTN / 8;
    constexpr int ATILE  = BM * 80;
    constexpr int BPITCH = (BN + 8) * 2;
    constexpr int BTILE  = 32 * BPITCH;
    constexpr int STAGE  = ATILE + BTILE;

    const uint32_t smb = smem_u32(sm);
    const int tid = threadIdx.x, lane = tid & 31, wid = tid >> 5;
    const int wm = wid / WN, wn = wid % WN;
    const int bm = blockIdx.y * BM, bn = blockIdx.x * BN;
    const size_t zA = (size_t)blockIdx.z * sAz, zB = (size_t)blockIdx.z * sBz;
    const __half* pA = Ah + zA + (size_t)bm * K;
    const __half* pB = Bh + zB;

    float acc[MF][NF][4];
#pragma unroll
    for (int i = 0; i < MF; i++)
#pragma unroll
        for (int j = 0; j < NF; j++)
#pragma unroll
            for (int q = 0; q < 4; q++) acc[i][j][q] = 0.f;

    const uint32_t a_off = (uint32_t)(lane & 15) * 80 + (uint32_t)(lane >> 4) * 16;
    const uint32_t b_off = (uint32_t)(lane & 15) * BPITCH + (uint32_t)(lane >> 4) * 16;

    const int KT = K >> 5;

    auto load_stage = [&](int s, int kt) {
        const int k0 = kt << 5;
        const uint32_t base = smb + s * STAGE;
#pragma unroll 2
        for (int cid = tid; cid < BM * 4; cid += 256) {
            const int row = cid >> 2, p = cid & 3;
            CPA(base + row * 80 + p * 16, pA + (size_t)row * K + k0 + p * 8);
        }
#pragma unroll 2
        for (int cid = tid; cid < 32 * (BN / 8); cid += 256) {
            const int row = cid / (BN / 8), c = cid % (BN / 8);
            CPA(base + ATILE + row * BPITCH + c * 16,
                pB + (size_t)(k0 + row) * N + bn + c * 8);
        }
    };

    load_stage(0, 0); CPC();
    if (KT > 1) { load_stage(1, 1); CPC(); }

    for (int kt = 0; kt < KT; ++kt) {
        const int stg = kt & 3;
        if (kt + 2 < KT) { load_stage((kt + 2) & 3, kt + 2); CPC(); CPW(2); }
        else if (kt + 1 < KT) CPW(1);
        else CPW(0);
        __syncthreads();

        const uint32_t stageB = smb + stg * STAGE;
        const uint32_t aB = stageB + wm * 32 * 80 + a_off;
        const uint32_t bB = stageB + ATILE + wn * WTN * 2 + b_off;
#pragma unroll
        for (int ks = 0; ks < 2; ++ks) {
            uint32_t aR[MF][4], bR[(NF + 1) / 2][4];
#pragma unroll
            for (int n2 = 0; n2 < NF / 2; n2++)
                ldsm4t(bR[n2], bB + ks * 16 * BPITCH + n2 * 32);
#pragma unroll
            for (int mi = 0; mi < MF; mi++)
                ldsm4(aR[mi], aB + mi * 16 * 80 + ks * 32);

#pragma unroll
            for (int mi = 0; mi < MF; mi++)
#pragma unroll
                for (int n2 = 0; n2 < NF / 2; n2++) {
                    mma_f16(acc[mi][n2 * 2],     aR[mi], &bR[n2][0]);
                    mma_f16(acc[mi][n2 * 2 + 1], aR[mi], &bR[n2][2]);
                }
        }
    }

    // ---- epilogue ----
    const float sc = (blockIdx.z == 0) ? scale0 : scale;
    const size_t cz = (size_t)blockIdx.z * sCz;
    const float* bz = bias ? bias + (size_t)blockIdx.z * bsz : nullptr;
    const int r0 = bm + wm * 32 + (lane >> 2);
    const int c0 = bn + wn * WTN + (lane & 3) * 2;

#pragma unroll
    for (int mi = 0; mi < MF; mi++) {
#pragma unroll
        for (int ni = 0; ni < NF; ni++) {
            const int col = c0 + ni * 8;
#pragma unroll
            for (int half = 0; half < 2; half++) {
                const int row = r0 + mi * 16 + half * 8;
                float v0 = acc[mi][ni][half * 2]     * sc;
                float v1 = acc[mi][ni][half * 2 + 1] * sc;
                if (bz) { v0 += bz[col]; v1 += bz[col + 1]; }
                if (relu) { v0 = fmaxf(v0, 0.f); v1 = fmaxf(v1, 0.f); }
                if (res) {
                    const float2 rv = *(const float2*)&res[(size_t)row * N + col];
                    v0 += rv.x; v1 += rv.y;
                }
                const size_t o = cz + (size_t)row * N + col;
                if (Cf) { float2 f = {v0, v1}; *(float2*)&Cf[o] = f; }
                if (Chi) {
                    float2 fv; fv.x = v0; fv.y = v1;
                    *(__half2*)&Chi[o] = __float22half2_rn(fv);
                }
            }
        }
    }
}

// ================= fused attention — single barrier per KV tile =================
#define APITCH 144
#define QBYTES (128*APITCH)
#define TBYTES (64*APITCH)
#define AT_SMEM (QBYTES + 4*TBYTES)  // 55296 -> 3 CTAs/SM

__global__ void __launch_bounds__(256, 3)
k_attn(const __half* __restrict__ q, const __half* __restrict__ k,
       const __half* __restrict__ v, __half* __restrict__ och) {
    extern __shared__ char sm[];
    const uint32_t smb = smem_u32(sm);
    const uint32_t KOFF = QBYTES, VOFF = QBYTES + 2 * TBYTES;
    const int tid = threadIdx.x, lane = tid & 31, w = tid >> 5;
    const int z = blockIdx.y, qb = blockIdx.x;
    const __half* pQ = q + (size_t)z * HSZ + (size_t)qb * 128 * DH;
    const __half* pK = k + (size_t)z * HSZ;
    const __half* pV = v + (size_t)z * HSZ;

    const uint32_t a_off  = (uint32_t)(lane & 15) * APITCH + (uint32_t)(lane >> 4) * 16;
    const uint32_t bs_off = (uint32_t)((lane & 7) + ((lane >> 1) & 8)) * APITCH
                          + (uint32_t)((lane >> 3) & 1) * 16;
    const uint32_t bt_off = a_off;

    auto loadQ = [&]() {
#pragma unroll
        for (int cid = tid; cid < 1024; cid += 256) {
            const int row = cid >> 3, p = cid & 7;
            CPA(smb + row * APITCH + p * 16, pQ + (size_t)row * DH + p * 8);
        }
    };
    auto loadKV = [&](int t) {
        const uint32_t kb = smb + KOFF + (t & 1) * TBYTES;
        const uint32_t vb = smb + VOFF + (t & 1) * TBYTES;
        const __half* sk = pK + (size_t)t * 64 * DH;
        const __half* sv = pV + (size_t)t * 64 * DH;
#pragma unroll
        for (int cid = tid; cid < 512; cid += 256) {
            const int row = cid >> 3, p = cid & 7;
            CPA(kb + row * APITCH + p * 16, sk + (size_t)row * DH + p * 8);
            CPA(vb + row * APITCH + p * 16, sv + (size_t)row * DH + p * 8);
        }
    };

    loadQ(); loadKV(0); CPC();

    float oacc[8][4];
#pragma unroll
    for (int j = 0; j < 8; j++)
#pragma unroll
        for (int qq = 0; qq < 4; qq++) oacc[j][qq] = 0.f;
    float l0 = 0.f, l1 = 0.f;

    const uint32_t qbase = smb + w * 16 * APITCH + a_off;
    const __half2 clampv = __floats2half2_rn(14.f, 14.f);

    for (int t = 0; t < 8; ++t) {
        // one barrier per tile: drain tile t's loads, sync, then issue t+1's
        // loads into stage (t+1)&1 == (t-1)&1 — all warps finished reading that
        // stage at iteration t-1 and have crossed this barrier since.
        CPW(0);
        __syncthreads();
        if (t + 1 < 8) { loadKV(t + 1); CPC(); }   // overlaps tile-t compute

        // ---- S = Q K^T (logits pre-scaled via Q) ----
        const uint32_t kbase = smb + KOFF + (t & 1) * TBYTES;
        float sacc[8][4];
#pragma unroll
        for (int j = 0; j < 8; j++)
#pragma unroll
            for (int qq = 0; qq < 4; qq++) sacc[j][qq] = 0.f;
#pragma unroll
        for (int kc = 0; kc < 4; kc++) {
            uint32_t qf[4];
            ldsm4(qf, qbase + kc * 32);
#pragma unroll
            for (int n2 = 0; n2 < 4; n2++) {
                uint32_t kb[4];
                ldsm4(kb, kbase + n2 * 16 * APITCH + kc * 32 + bs_off);
                mma_f16(sacc[n2 * 2],     qf, &kb[0]);
                mma_f16(sacc[n2 * 2 + 1], qf, &kb[2]);
            }
        }

        // ---- P = exp2(clamp(S)) fp16x2; l += sums ----
        uint32_t pp0[8], pp1[8];
#pragma unroll
        for (int j = 0; j < 8; j++) {
            __half2 a = __floats2half2_rn(sacc[j][0], sacc[j][1]);
            __half2 b = __floats2half2_rn(sacc[j][2], sacc[j][3]);
            a = __hmin2(a, clampv);
            b = __hmin2(b, clampv);
            pp0[j] = ex2_h2(*(const uint32_t*)&a);
            pp1[j] = ex2_h2(*(const uint32_t*)&b);
            const float2 fa = __half22float2(*(const __half2*)&pp0[j]);
            const float2 fb = __half22float2(*(const __half2*)&pp1[j]);
            l0 += fa.x + fa.y;
            l1 += fb.x + fb.y;
        }

        // ---- O += P V ----
        const uint32_t vbase = smb + VOFF + (t & 1) * TBYTES;
#pragma unroll
        for (int kc = 0; kc < 4; kc++) {
            uint32_t pa[4];
            pa[0] = pp0[2 * kc];     pa[1] = pp1[2 * kc];
            pa[2] = pp0[2 * kc + 1]; pa[3] = pp1[2 * kc + 1];
#pragma unroll
            for (int n2 = 0; n2 < 4; n2++) {
                uint32_t vb[4];
                ldsm4t(vb, vbase + kc * 16 * APITCH + n2 * 32 + bt_off);
                mma_f16(oacc[n2 * 2],     pa, &vb[0]);
                mma_f16(oacc[n2 * 2 + 1], pa, &vb[2]);
            }
        }
    }

#pragma unroll
    for (int off = 1; off <= 2; off <<= 1) {
        l0 += __shfl_xor_sync(~0u, l0, off);
        l1 += __shfl_xor_sync(~0u, l1, off);
    }
    const float inv0 = 1.f / l0, inv1 = 1.f / l1;
    const int r0 = qb * 128 + w * 16 + (lane >> 2);
    __half* po = och + (size_t)z * HSZ;
#pragma unroll
    for (int j = 0; j < 8; j++) {
        const int col = j * 8 + (lane & 3) * 2;
        *(__half2*)(po + (size_t)r0 * DH + col) =
            __floats2half2_rn(oacc[j][0] * inv0, oacc[j][1] * inv0);
        *(__half2*)(po + (size_t)(r0 + 8) * DH + col) =
            __floats2half2_rn(oacc[j][2] * inv1, oacc[j][3] * inv1);
    }
}

// ------- fused weight fp16 convert + qkv bias pack + Wc transpose -------
__global__ void k_prep(const float* __restrict__ Wq, const float* __restrict__ Wk,
                       const float* __restrict__ Wv, const float* __restrict__ Wo,
                       const float* __restrict__ W1, const float* __restrict__ W2,
                       __half* __restrict__ wh,
                       const float* __restrict__ bq, const float* __restrict__ bk,
                       const float* __restrict__ bv, float* __restrict__ bqkv,
                       const float* __restrict__ Wc, float* __restrict__ wct) {
    const int l = blockIdx.y;
    // bias pack (blocks 0..8 of every layer)
    if (blockIdx.x < 9) {
        const int j = blockIdx.x * 256 + threadIdx.x;
        if (j < 3 * E) {
            float val;
            if (j < E)            val = bq[(size_t)l * E + j] * C_EXP2;
            else if (j < 2 * E)   val = bk[(size_t)l * E + j - E];
            else                  val = bv[(size_t)l * E + j - 2 * E];
            bqkv[(size_t)l * 3 * E + j] = val;
        }
    }
    // classifier weight transpose (layer-0 blocks 0..1535 cover SE/256 row blocks)
    if (l == 0 && blockIdx.x < SE / 256) {
        __shared__ float tbuf[2560];
        const int i0 = blockIdx.x * 256;
        for (int j = threadIdx.x; j < 2560; j += 256)
            tbuf[j] = Wc[(size_t)i0 * CC + j];
        __syncthreads();
        for (int c = 0; c < CC; c++)
            wct[(size_t)c * SE + i0 + threadIdx.x] = tbuf[threadIdx.x * CC + c];
    }
    const size_t i = ((size_t)blockIdx.x * 256 + threadIdx.x) * 16;
    if (i >= LW) return;
    const float* src;
    if (i < 4 * (size_t)EE) {
        const int ty = (int)(i / EE);
        const float* base = (ty == 0) ? Wq : (ty == 1) ? Wk : (ty == 2) ? Wv : Wo;
        src = base + (size_t)l * EE + (i - (size_t)ty * EE);
    } else if (i < (size_t)OFF_2) {
        src = W1 + (size_t)l * EF + (i - OFF_1);
    } else {
        src = W2 + (size_t)l * EF + (i - OFF_2);
    }
    uint32_t hi[8];
#pragma unroll
    for (int g4 = 0; g4 < 4; g4++) {
        const float4 v = *(const float4*)(src + g4 * 4);
        const __half2 h0 = __floats2half2_rn(v.x, v.y);
        const __half2 h1 = __floats2half2_rn(v.z, v.w);
        hi[g4 * 2]     = *(const uint32_t*)&h0;
        hi[g4 * 2 + 1] = *(const uint32_t*)&h1;
    }
    __half* dst = wh + (size_t)l * LW + i;
    *(uint4*)dst       = *(uint4*)hi;
    *(uint4*)(dst + 8) = *(uint4*)(hi + 4);
}

// ---------------- embedding gather ----------------
__global__ void k_embed(const int* __restrict__ x, const float* __restrict__ emb,
                        float* __restrict__ h, __half* __restrict__ hh) {
    const int row = blockIdx.x;
    const int tok = x[row];
    for (int i = threadIdx.x; i < E; i += 256) {
        const float v = emb[(size_t)tok * E + i];
        const size_t o = (size_t)row * E + i;
        h[o] = v;
        hh[o] = __float2half(v);
    }
}

// ---------------- layernorm: fp32 in, fp32 + fp16 out, warp per row ----------
__global__ void k_ln(const float* __restrict__ in, float* __restrict__ out,
                     __half* __restrict__ oh,
                     const float* __restrict__ g, const float* __restrict__ b) {
    const int w = threadIdx.x >> 5, lane = threadIdx.x & 31;
    const int row = blockIdx.x * 8 + w;
    const float* p = in + (size_t)row * E;

    float4 x[6];
    float s = 0.f, q = 0.f;
#pragma unroll
    for (int i = 0; i < 6; i++) {
        x[i] = *(const float4*)(p + 4 * (lane + 32 * i));
        s += x[i].x + x[i].y + x[i].z + x[i].w;
        q += x[i].x * x[i].x + x[i].y * x[i].y + x[i].z * x[i].z + x[i].w * x[i].w;
    }
#pragma unroll
    for (int off = 16; off; off >>= 1) {
        s += __shfl_xor_sync(~0u, s, off);
        q += __shfl_xor_sync(~0u, q, off);
    }
    const float mean = s * (1.0f / E);
    const float var  = q * (1.0f / E) - mean * mean;
    const float inv  = rsqrtf(var + EPSL);

    float* po = out + (size_t)row * E;
    __half* ph = oh + (size_t)row * E;
#pragma unroll
    for (int i = 0; i < 6; i++) {
        const int c4 = 4 * (lane + 32 * i);
        const float4 gv = *(const float4*)(g + c4);
        const float4 bv = *(const float4*)(b + c4);
        float4 v;
        v.x = (x[i].x - mean) * inv * gv.x + bv.x;
        v.y = (x[i].y - mean) * inv * gv.y + bv.y;
        v.z = (x[i].z - mean) * inv * gv.z + bv.z;
        v.w = (x[i].w - mean) * inv * gv.w + bv.w;
        *(float4*)(po + c4) = v;
        uint32_t hp[2];
        const __half2 h0 = __floats2half2_rn(v.x, v.y);
        const __half2 h1 = __floats2half2_rn(v.z, v.w);
        hp[0] = *(const uint32_t*)&h0;
        hp[1] = *(const uint32_t*)&h1;
        *(uint2*)(ph + c4) = *(uint2*)hp;
    }
}

// ---------------- classifier: coalesced via WcT ----------------
#define CLS_P 37
#define CLS_CHUNK 10752
__global__ void k_cls1(const float* __restrict__ h, const float* __restrict__ wct,
                       float* __restrict__ part) {
    __shared__ float red[256];
    const int bb = blockIdx.x, p = blockIdx.y, t = threadIdx.x;
    const float* hr = h + (size_t)bb * SE;
    const int i0 = p * CLS_CHUNK;
    const int iend = (i0 + CLS_CHUNK < SE) ? i0 + CLS_CHUNK : SE;
    float a[CC];
#pragma unroll
    for (int c = 0; c < CC; c++) a[c] = 0.f;
    for (int i = i0 + t * 4; i < iend; i += 1024) {
        const float4 hv = *(const float4*)&hr[i];
#pragma unroll
        for (int c = 0; c < CC; c++) {
            const float4 wv = *(const float4*)&wct[(size_t)c * SE + i];
            a[c] = fmaf(hv.x, wv.x, fmaf(hv.y, wv.y, fmaf(hv.z, wv.z, fmaf(hv.w, wv.w, a[c]))));
        }
    }
#pragma unroll
    for (int c = 0; c < CC; c++) {
        red[t] = a[c]; __syncthreads();
        for (int k = 128; k > 0; k >>= 1) {
            if (t < k) red[t] += red[t + k];
            __syncthreads();
        }
        if (t == 0) part[((size_t)bb * CLS_P + p) * CC + c] = red[0];
        __syncthreads();
    }
}
__global__ void k_cls2(const float* __restrict__ part, const float* __restrict__ bc,
                       float* __restrict__ out) {
    const int t = threadIdx.x;
    if (t < B * CC) {
        const int bb = t / CC, c = t % CC;
        float s = bc[c];
        for (int p = 0; p < CLS_P; p++) s += part[((size_t)bb * CLS_P + p) * CC + c];
        out[t] = s;
    }
}

// ---------------- host ----------------
extern "C" void kernel_launch(void* const* d_in, const int* in_sizes, int n_in,
                              void* d_out, int out_size) {
    const int*   x    = (const int*)  d_in[0];
    const float* emb  = (const float*)d_in[1];
    const float* Wq   = (const float*)d_in[2];
    const float* bq   = (const float*)d_in[3];
    const float* Wk   = (const float*)d_in[4];
    const float* bk   = (const float*)d_in[5];
    const float* Wv   = (const float*)d_in[6];
    const float* bv   = (const float*)d_in[7];
    const float* Wo   = (const float*)d_in[8];
    const float* bo   = (const float*)d_in[9];
    const float* ln1g = (const float*)d_in[10];
    const float* ln1b = (const float*)d_in[11];
    const float* W1   = (const float*)d_in[12];
    const float* b1   = (const float*)d_in[13];
    const float* W2   = (const float*)d_in[14];
    const float* b2   = (const float*)d_in[15];
    const float* ln2g = (const float*)d_in[16];
    const float* ln2b = (const float*)d_in[17];
    const float* Wc   = (const float*)d_in[18];
    const float* bc   = (const float*)d_in[19];
    float* out = (float*)d_out;

    float *h, *t, *bqkv, *wct, *part;
    __half *hh, *qkv, *ch, *fh, *wh;
    cudaGetSymbolAddress((void**)&h,   g_h);
    cudaGetSymbolAddress((void**)&t,   g_t);
    cudaGetSymbolAddress((void**)&hh,  g_hh);
    cudaGetSymbolAddress((void**)&qkv, g_qkv);
    cudaGetSymbolAddress((void**)&ch,  g_ch);
    cudaGetSymbolAddress((void**)&fh,  g_fh);
    cudaGetSymbolAddress((void**)&wh,  g_wh);
    cudaGetSymbolAddress((void**)&bqkv, g_bqkv);
    cudaGetSymbolAddress((void**)&wct, g_wct);
    cudaGetSymbolAddress((void**)&part, g_part);

    constexpr int SMEM_QKV = 4 * (128 * 80 + 32 * (128 + 8) * 2);
    constexpr int SMEM_W   = 4 * (64 * 80 + 32 * (128 + 8) * 2);
    cudaFuncSetAttribute(k_mma<128, 128>, cudaFuncAttributeMaxDynamicSharedMemorySize, SMEM_QKV);
    cudaFuncSetAttribute(k_mma<64, 128>,  cudaFuncAttributeMaxDynamicSharedMemorySize, SMEM_W);
    cudaFuncSetAttribute(k_attn,          cudaFuncAttributeMaxDynamicSharedMemorySize, AT_SMEM);

    __half *qh = qkv, *kh = qkv + (size_t)M4 * E, *vh = qkv + (size_t)2 * M4 * E;

    k_prep<<<dim3(LW / 4096, L), 256>>>(Wq, Wk, Wv, Wo, W1, W2, wh,
                                        bq, bk, bv, bqkv, Wc, wct);
    k_embed<<<M4, 256>>>(x, emb, h, hh);

    const dim3 gQKV(6, 32, 3);
    const dim3 gEE64(6, 64);
    const dim3 gF164(24, 64);
    const dim3 gAt(4, NHEAD);

    for (int l = 0; l < L; l++) {
        const size_t wb = (size_t)l * LW;

        // fused QKV (q pre-scaled by 0.125*log2e)
        k_mma<128, 128><<<gQKV, 256, SMEM_QKV>>>(hh, wh + wb + OFF_Q,
            bqkv + (size_t)l * 3 * E, nullptr, nullptr, qkv,
            E, E, 0, (size_t)EE, (size_t)M4 * E, E, C_EXP2, 1.f, 0);

        // fused attention
        k_attn<<<gAt, 256, AT_SMEM>>>(qh, kh, vh, ch);

        // Wo + residual -> t (fp32) -> LN1
        k_mma<64, 128><<<gEE64, 256, SMEM_W>>>(ch, wh + wb + OFF_O,
            bo + (size_t)l * E, h, t, nullptr,
            E, E, 0, 0, 0, 0, 1.f, 1.f, 0);
        k_ln<<<M4 / 8, 256>>>(t, h, hh, ln1g + (size_t)l * E, ln1b + (size_t)l * E);

        // FFN
        k_mma<64, 128><<<gF164, 256, SMEM_W>>>(hh, wh + wb + OFF_1,
            b1 + (size_t)l * FF, nullptr, nullptr, fh,
            FF, E, 0, 0, 0, 0, 1.f, 1.f, 1);
        k_mma<64, 128><<<gEE64, 256, SMEM_W>>>(fh, wh + wb + OFF_2,
            b2 + (size_t)l * E, h, t, nullptr,
            E, FF, 0, 0, 0, 0, 1.f, 1.f, 0);
        k_ln<<<M4 / 8, 256>>>(t, h, hh, ln2g + (size_t)l * E, ln2b + (size_t)l * E);
    }

    // classifier (fp32 exact, coalesced)
    k_cls1<<<dim3(B, CLS_P), 256>>>(h, wct, part);
    k_cls2<<<1, 128>>>(part, bc, out);
}